// round 14
// baseline (speedup 1.0000x reference)
#include <cuda_runtime.h>
#include <cuda_fp16.h>
#include <cstdint>

#define NN   50000
#define EE   800000
#define FIN  128
#define FH   128
#define FOUT 32
#define KCH  16

// ---------------- device scratch ----------------
__device__ float  g_S1[NN * (KCH * FH)];    // 50000 x 2048
__device__ float  g_S2[NN * (KCH * FOUT)];  // 50000 x 512
__device__ __half g_Xh[NN * FIN];           // fp16 x
__device__ __half g_W1t[(KCH * FH) * FIN];  // W1 transposed: [n][k]
__device__ __half g_W2t[(KCH * FOUT) * FH]; // W2 transposed
__device__ __half g_h0[NN * FH];
__device__ __half g_h1[NN * FH];
__device__ __half g_h2[NN * FH];
__device__ __half g_h3[NN * FH];            // extra ring buffer (layer-2 race fix)
__device__ float  g_H [NN * FH];
__device__ int    g_degi[NN];
__device__ int    g_cnt [NN];
__device__ int    g_rowptr[NN + 1];
__device__ int    g_cursor[NN];
__device__ float  g_dinv[NN];
__device__ int2   g_colval[EE];
__device__ float  g_bnsum1[FH];
__device__ float  g_bnsq1 [FH];
__device__ float  g_bnsum2[FOUT];
__device__ float  g_bnsq2 [FOUT];
__device__ int    g_is32;

// ---------------- helpers ----------------
__device__ __forceinline__ void mma_f16(float* c, const unsigned* a, const unsigned* b) {
    asm volatile("mma.sync.aligned.m16n8k16.row.col.f32.f16.f16.f32 "
        "{%0,%1,%2,%3}, {%4,%5,%6,%7}, {%8,%9}, {%0,%1,%2,%3};"
        : "+f"(c[0]), "+f"(c[1]), "+f"(c[2]), "+f"(c[3])
        : "r"(a[0]), "r"(a[1]), "r"(a[2]), "r"(a[3]), "r"(b[0]), "r"(b[1]));
}

__device__ __forceinline__ void cp_async16(uint32_t dst, const void* src, int szbytes) {
    asm volatile("cp.async.cg.shared.global [%0], [%1], 16, %2;"
                 :: "r"(dst), "l"(src), "r"(szbytes));
}
__device__ __forceinline__ void cp_commit() {
    asm volatile("cp.async.commit_group;");
}
template <int NW>
__device__ __forceinline__ void cp_wait() {
    asm volatile("cp.async.wait_group %0;" :: "n"(NW));
}

// ---------------- build kernels ----------------
__global__ void init_zero(int N) {
    int i = blockIdx.x * blockDim.x + threadIdx.x;
    if (i < N) { g_degi[i] = 0; g_cnt[i] = 0; }
    if (i < FH)   { g_bnsum1[i] = 0.f; g_bnsq1[i] = 0.f; }
    if (i < FOUT) { g_bnsum2[i] = 0.f; g_bnsq2[i] = 0.f; }
    if (i == 0) g_is32 = 0;
}

__global__ void detect_dtype(const int* __restrict__ p, int E) {
    int i = blockIdx.x * blockDim.x + threadIdx.x;
    if (i < E) {
        if (p[2 * i + 1] != 0) g_is32 = 1;
    }
}

__global__ void cvt_xh(const float2* __restrict__ x, __half2* __restrict__ xh, int n2) {
    int i = blockIdx.x * blockDim.x + threadIdx.x;
    if (i >= n2) return;
    float2 v = x[i];
    xh[i] = __floats2half2_rn(v.x, v.y);
}

__device__ __forceinline__ void load_edge(const void* ei, int E, int e, int& s, int& d) {
    if (g_is32) {
        const int* p = (const int*)ei;
        s = p[e]; d = p[E + e];
    } else {
        const long long* p = (const long long*)ei;
        s = (int)p[e]; d = (int)p[E + e];
    }
}

__global__ void degree_kernel(const void* __restrict__ ei, int E) {
    int e = blockIdx.x * blockDim.x + threadIdx.x;
    if (e >= E) return;
    int s, d; load_edge(ei, E, e, s, d);
    if (s != d) { atomicAdd(&g_degi[s], 1); atomicAdd(&g_cnt[d], 1); }
}

__global__ void dinv_kernel(int N) {
    int i = blockIdx.x * blockDim.x + threadIdx.x;
    if (i >= N) return;
    int dg = g_degi[i];
    g_dinv[i] = (dg > 0) ? rsqrtf((float)dg) : 0.f;
}

__global__ void scan_kernel(int N) {
    __shared__ int warpsum[32];
    __shared__ int s_carry;
    __shared__ int s_chunk;
    int t = threadIdx.x, lane = t & 31, wid = t >> 5;
    if (t == 0) s_carry = 0;
    __syncthreads();
    for (int base = 0; base < N; base += 1024) {
        int idx = base + t;
        int v = (idx < N) ? g_cnt[idx] : 0;
        int x = v;
        #pragma unroll
        for (int off = 1; off < 32; off <<= 1) {
            int y = __shfl_up_sync(0xffffffffu, x, off);
            if (lane >= off) x += y;
        }
        if (lane == 31) warpsum[wid] = x;
        __syncthreads();
        if (wid == 0) {
            int w = warpsum[lane];
            int xw = w;
            #pragma unroll
            for (int off = 1; off < 32; off <<= 1) {
                int y = __shfl_up_sync(0xffffffffu, xw, off);
                if (lane >= off) xw += y;
            }
            warpsum[lane] = xw - w;
            if (lane == 31) s_chunk = xw;
        }
        __syncthreads();
        int excl = s_carry + warpsum[wid] + x - v;
        if (idx < N) { g_rowptr[idx] = excl; g_cursor[idx] = excl; }
        __syncthreads();
        if (t == 0) s_carry += s_chunk;
        __syncthreads();
    }
    if (threadIdx.x == 0) g_rowptr[N] = s_carry;
}

__global__ void scatter_kernel(const void* __restrict__ ei, int E) {
    int e = blockIdx.x * blockDim.x + threadIdx.x;
    if (e >= E) return;
    int s, d; load_edge(ei, E, e, s, d);
    if (s != d) {
        int pos = atomicAdd(&g_cursor[d], 1);
        float v = -g_dinv[s] * g_dinv[d];
        g_colval[pos] = make_int2(s, __float_as_int(v));
    }
}

// ---------------- weight concat: transpose to [n][k] fp16 ----------------
__global__ void concat_w1_t(const float* __restrict__ W, __half* __restrict__ Wt) {
    int j = blockIdx.x * blockDim.x + threadIdx.x;
    if (j >= (KCH * FH) * FIN) return;
    int n = j >> 7;
    int f = j & 127;
    int k = n >> 7;
    int o = n & 127;
    Wt[j] = __float2half_rn(W[k * (FIN * FH) + f * FH + o]);
}

__global__ void concat_w2_t(const float* __restrict__ W, __half* __restrict__ Wt) {
    int j = blockIdx.x * blockDim.x + threadIdx.x;
    if (j >= (KCH * FOUT) * FH) return;
    int n = j >> 7;
    int f = j & 127;
    int k = n >> 5;
    int o = n & 31;
    Wt[j] = __float2half_rn(W[k * (FH * FOUT) + f * FOUT + o]);
}

// ---------------- FP16 GEMM: C[N,NC] = A[N,128] @ Bt[NC,128]^T ----------------
#define SH_STRIDE 40
#define SA_STAGE_B (128 * SH_STRIDE * 2)
#define SB_STAGE_B (128 * SH_STRIDE * 2)
#define GEMM_SMEM (2 * (SA_STAGE_B + SB_STAGE_B))

__global__ __launch_bounds__(256, 2) void gemm_f16(const __half* __restrict__ A,
                                                   const __half* __restrict__ Bt,
                                                   float* __restrict__ C,
                                                   int N, int NC) {
    extern __shared__ char smem[];
    char* sA = smem;
    char* sB = smem + 2 * SA_STAGE_B;
    uint32_t sA_u = (uint32_t)__cvta_generic_to_shared(sA);
    uint32_t sB_u = (uint32_t)__cvta_generic_to_shared(sB);

    int t = threadIdx.x;
    int lane = t & 31;
    int warp = t >> 5;
    int tig = lane & 3;
    int grp = lane >> 2;
    int wm0 = (warp & 1) * 64;
    int wn0 = (warp >> 1) * 32;
    int bm0 = blockIdx.x * 128;
    int bn0 = blockIdx.y * 128;

    float c[4][4][4];
    #pragma unroll
    for (int mi = 0; mi < 4; mi++)
        #pragma unroll
        for (int ni = 0; ni < 4; ni++)
            #pragma unroll
            for (int r = 0; r < 4; r++) c[mi][ni][r] = 0.f;

    auto prefetch = [&](int stage, int kt) {
        #pragma unroll
        for (int i = 0; i < 2; i++) {
            int id = t + i * 256;
            int row = id >> 2, c4 = id & 3;
            int gr = bm0 + row;
            int ok = (gr < N);
            int grs = ok ? gr : 0;
            uint32_t dst = sA_u + stage * SA_STAGE_B + row * 80 + c4 * 16;
            cp_async16(dst, &A[(size_t)grs * 128 + kt + c4 * 8], ok ? 16 : 0);
        }
        #pragma unroll
        for (int i = 0; i < 2; i++) {
            int id = t + i * 256;
            int row = id >> 2, c4 = id & 3;
            uint32_t dst = sB_u + stage * SB_STAGE_B + row * 80 + c4 * 16;
            cp_async16(dst, &Bt[(size_t)(bn0 + row) * 128 + kt + c4 * 8], 16);
        }
        cp_commit();
    };

    prefetch(0, 0);

    #pragma unroll
    for (int it = 0; it < 4; it++) {
        if (it < 3) prefetch((it + 1) & 1, (it + 1) * 32);
        if (it < 3) cp_wait<1>(); else cp_wait<0>();
        __syncthreads();

        const unsigned* cA = (const unsigned*)(sA + (it & 1) * SA_STAGE_B);
        const unsigned* cB = (const unsigned*)(sB + (it & 1) * SB_STAGE_B);
        #pragma unroll
        for (int kh = 0; kh < 2; kh++) {
            int ko = kh * 8;
            unsigned a[4][4], b[4][2];
            #pragma unroll
            for (int mi = 0; mi < 4; mi++) {
                int row = wm0 + mi * 16 + grp;
                int base = row * 20 + ko + tig;
                a[mi][0] = cA[base];
                a[mi][1] = cA[base + 8 * 20];
                a[mi][2] = cA[base + 4];
                a[mi][3] = cA[base + 8 * 20 + 4];
            }
            #pragma unroll
            for (int ni = 0; ni < 4; ni++) {
                int nn = wn0 + ni * 8 + grp;
                int nb = nn * 20 + ko + tig;
                b[ni][0] = cB[nb];
                b[ni][1] = cB[nb + 4];
            }
            #pragma unroll
            for (int mi = 0; mi < 4; mi++)
                #pragma unroll
                for (int ni = 0; ni < 4; ni++)
                    mma_f16(c[mi][ni], a[mi], b[ni]);
        }
        __syncthreads();
    }

    #pragma unroll
    for (int mi = 0; mi < 4; mi++) {
        #pragma unroll
        for (int ni = 0; ni < 4; ni++) {
            int gr = bm0 + wm0 + mi * 16 + grp;
            int gc = bn0 + wn0 + ni * 8 + 2 * tig;
            if (gr < N)
                *(float2*)&C[(size_t)gr * NC + gc] = make_float2(c[mi][ni][0], c[mi][ni][1]);
            if (gr + 8 < N)
                *(float2*)&C[(size_t)(gr + 8) * NC + gc] = make_float2(c[mi][ni][2], c[mi][ni][3]);
        }
    }
}

// ---------------- Clenshaw SpMM, 128 features, fp16 chain ----------------
template <int USEH>
__global__ void cheb_spmm128(const uint2* __restrict__ b1h,
                             const float4* __restrict__ b1f, int ldb1f,
                             const uint2* __restrict__ b2h,
                             const float4* __restrict__ b2f, int ldb2f,
                             const float4* __restrict__ S, int ldS,
                             uint2* __restrict__ dsth,
                             float4* __restrict__ dstf,
                             const float4* __restrict__ bias,
                             float two, int N, int stats) {
    __shared__ float ssum[128], ssq[128];
    int row = (blockIdx.x * blockDim.x + threadIdx.x) >> 5;
    int lane = threadIdx.x & 31;
    if (stats) {
        if (threadIdx.x < 128) { ssum[threadIdx.x] = 0.f; ssq[threadIdx.x] = 0.f; }
        __syncthreads();
    }
    if (row < N) {
        int start = g_rowptr[row], end = g_rowptr[row + 1];
        float4 acc = make_float4(0.f, 0.f, 0.f, 0.f);
        for (int i = start; i < end; i += 32) {
            int nb = min(32, end - i);
            int c = 0; float v = 0.f;
            if (lane < nb) {
                int2 cv = g_colval[i + lane];
                c = cv.x; v = __int_as_float(cv.y);
            }
            #pragma unroll 4
            for (int j = 0; j < nb; j++) {
                int   cc = __shfl_sync(0xffffffffu, c, j);
                float vv = __shfl_sync(0xffffffffu, v, j);
                if (USEH) {
                    uint2 u = b1h[(size_t)cc * 32 + lane];
                    float2 f01 = __half22float2(*(const __half2*)&u.x);
                    float2 f23 = __half22float2(*(const __half2*)&u.y);
                    acc.x = fmaf(vv, f01.x, acc.x);
                    acc.y = fmaf(vv, f01.y, acc.y);
                    acc.z = fmaf(vv, f23.x, acc.z);
                    acc.w = fmaf(vv, f23.y, acc.w);
                } else {
                    float4 xr = b1f[(size_t)cc * ldb1f + lane];
                    acc.x = fmaf(vv, xr.x, acc.x);
                    acc.y = fmaf(vv, xr.y, acc.y);
                    acc.z = fmaf(vv, xr.z, acc.z);
                    acc.w = fmaf(vv, xr.w, acc.w);
                }
            }
        }
        float4 s = S[(size_t)row * ldS + lane];
        float4 r;
        r.x = fmaf(two, acc.x, s.x);
        r.y = fmaf(two, acc.y, s.y);
        r.z = fmaf(two, acc.z, s.z);
        r.w = fmaf(two, acc.w, s.w);
        if (b2h) {
            uint2 u = b2h[(size_t)row * 32 + lane];
            float2 f01 = __half22float2(*(const __half2*)&u.x);
            float2 f23 = __half22float2(*(const __half2*)&u.y);
            r.x -= f01.x; r.y -= f01.y; r.z -= f23.x; r.w -= f23.y;
        } else if (b2f) {
            float4 tt = b2f[(size_t)row * ldb2f + lane];
            r.x -= tt.x; r.y -= tt.y; r.z -= tt.z; r.w -= tt.w;
        }
        if (bias) {
            float4 bb = bias[lane];
            r.x += bb.x; r.y += bb.y; r.z += bb.z; r.w += bb.w;
        }
        if (dsth) {
            __half2 h01 = __floats2half2_rn(r.x, r.y);
            __half2 h23 = __floats2half2_rn(r.z, r.w);
            uint2 u;
            u.x = *(unsigned*)&h01;
            u.y = *(unsigned*)&h23;
            dsth[(size_t)row * 32 + lane] = u;
        }
        if (dstf) dstf[(size_t)row * 32 + lane] = r;
        if (stats) {
            int f = lane * 4;
            atomicAdd(&ssum[f],     r.x); atomicAdd(&ssq[f],     r.x * r.x);
            atomicAdd(&ssum[f + 1], r.y); atomicAdd(&ssq[f + 1], r.y * r.y);
            atomicAdd(&ssum[f + 2], r.z); atomicAdd(&ssq[f + 2], r.z * r.z);
            atomicAdd(&ssum[f + 3], r.w); atomicAdd(&ssq[f + 3], r.w * r.w);
        }
    }
    if (stats) {
        __syncthreads();
        if (threadIdx.x < 128) {
            atomicAdd(&g_bnsum1[threadIdx.x], ssum[threadIdx.x]);
            atomicAdd(&g_bnsq1 [threadIdx.x], ssq [threadIdx.x]);
        }
    }
}

// ---------------- Clenshaw SpMM, 32 features, fp16 chain ----------------
template <int USEH>
__global__ void cheb_spmm32(const __half* __restrict__ b1h,
                            const float* __restrict__ b1f, int ldb1f,
                            const __half* __restrict__ b2h,
                            const float* __restrict__ b2f, int ldb2f,
                            const float* __restrict__ S, int ldS,
                            __half* __restrict__ dsth,
                            float* __restrict__ dstf,
                            const float* __restrict__ bias,
                            float two, int N, int stats) {
    __shared__ float ssum[32], ssq[32];
    int row = (blockIdx.x * blockDim.x + threadIdx.x) >> 5;
    int lane = threadIdx.x & 31;
    if (stats) {
        if (threadIdx.x < 32) { ssum[threadIdx.x] = 0.f; ssq[threadIdx.x] = 0.f; }
        __syncthreads();
    }
    if (row < N) {
        int start = g_rowptr[row], end = g_rowptr[row + 1];
        float acc = 0.f;
        for (int i = start; i < end; i += 32) {
            int nb = min(32, end - i);
            int c = 0; float v = 0.f;
            if (lane < nb) {
                int2 cv = g_colval[i + lane];
                c = cv.x; v = __int_as_float(cv.y);
            }
            #pragma unroll 4
            for (int j = 0; j < nb; j++) {
                int   cc = __shfl_sync(0xffffffffu, c, j);
                float vv = __shfl_sync(0xffffffffu, v, j);
                float xv;
                if (USEH) xv = __half2float(b1h[(size_t)cc * 32 + lane]);
                else      xv = b1f[(size_t)cc * ldb1f + lane];
                acc = fmaf(vv, xv, acc);
            }
        }
        float r = fmaf(two, acc, S[(size_t)row * ldS + lane]);
        if (b2h)      r -= __half2float(b2h[(size_t)row * 32 + lane]);
        else if (b2f) r -= b2f[(size_t)row * ldb2f + lane];
        if (bias) r += bias[lane];
        if (dsth) dsth[(size_t)row * 32 + lane] = __float2half_rn(r);
        if (dstf) dstf[(size_t)row * 32 + lane] = r;
        if (stats) {
            atomicAdd(&ssum[lane], r);
            atomicAdd(&ssq [lane], r * r);
        }
    }
    if (stats) {
        __syncthreads();
        if (threadIdx.x < 32) {
            atomicAdd(&g_bnsum2[threadIdx.x], ssum[threadIdx.x]);
            atomicAdd(&g_bnsq2 [threadIdx.x], ssq [threadIdx.x]);
        }
    }
}

// ---------------- BatchNorm apply ----------------
__global__ void bn_apply_relu(const float* __restrict__ X,
                              float* __restrict__ Yf, __half* __restrict__ Yh,
                              const float* __restrict__ gamma, const float* __restrict__ beta,
                              const float* __restrict__ bnsum, const float* __restrict__ bnsq,
                              int N, int C, int mode) {
    int i = blockIdx.x * blockDim.x + threadIdx.x;
    if (i >= N * C) return;
    int c = i % C;
    float invN = 1.f / (float)N;
    float mu  = bnsum[c] * invN;
    float var = bnsq[c] * invN - mu * mu;
    float y = fmaf(gamma[c] * rsqrtf(var + 1e-5f), X[i] - mu, beta[c]);
    y = fmaxf(y, 0.f);
    if (mode) Yh[i] = __float2half_rn(y);
    else      Yf[i] = y;
}

// ---------------- host ----------------
extern "C" void kernel_launch(void* const* d_in, const int* in_sizes, int n_in,
                              void* d_out, int out_size) {
    const float* x    = (const float*)d_in[0];
    const void*  ei   = d_in[1];
    const float* W1   = (const float*)d_in[2];
    const float* b1v  = (const float*)d_in[3];
    const float* W2   = (const float*)d_in[4];
    const float* b2v  = (const float*)d_in[5];
    const float* g1   = (const float*)d_in[6];
    const float* be1  = (const float*)d_in[7];
    const float* g2   = (const float*)d_in[8];
    const float* be2  = (const float*)d_in[9];
    float* out = (float*)d_out;

    int N = in_sizes[0] / FIN;
    int E = in_sizes[1] / 2;

    void* pv;
    cudaGetSymbolAddress(&pv, g_S1);  float*  S1  = (float*)pv;
    cudaGetSymbolAddress(&pv, g_S2);  float*  S2  = (float*)pv;
    cudaGetSymbolAddress(&pv, g_Xh);  __half* Xh  = (__half*)pv;
    cudaGetSymbolAddress(&pv, g_W1t); __half* W1t = (__half*)pv;
    cudaGetSymbolAddress(&pv, g_W2t); __half* W2t = (__half*)pv;
    cudaGetSymbolAddress(&pv, g_h0);  __half* H0  = (__half*)pv;
    cudaGetSymbolAddress(&pv, g_h1);  __half* H1  = (__half*)pv;
    cudaGetSymbolAddress(&pv, g_h2);  __half* H2  = (__half*)pv;
    cudaGetSymbolAddress(&pv, g_h3);  __half* H3  = (__half*)pv;
    cudaGetSymbolAddress(&pv, g_H);   float*  H   = (float*)pv;
    cudaGetSymbolAddress(&pv, g_bnsum1); float* bns1 = (float*)pv;
    cudaGetSymbolAddress(&pv, g_bnsq1);  float* bnq1 = (float*)pv;
    cudaGetSymbolAddress(&pv, g_bnsum2); float* bns2 = (float*)pv;
    cudaGetSymbolAddress(&pv, g_bnsq2);  float* bnq2 = (float*)pv;

    static int init_done = 0;
    static cudaStream_t s_side = nullptr;
    static cudaEvent_t s_evFork = nullptr, s_evJoin = nullptr;
    static cudaEvent_t s_evPrep1 = nullptr, s_evLo1 = nullptr;
    static cudaEvent_t s_evPrep2 = nullptr, s_evLo2 = nullptr;
    if (!init_done) {
        cudaFuncSetAttribute(gemm_f16, cudaFuncAttributeMaxDynamicSharedMemorySize, GEMM_SMEM);
        cudaStreamCreateWithFlags(&s_side, cudaStreamNonBlocking);
        cudaEventCreateWithFlags(&s_evFork, cudaEventDisableTiming);
        cudaEventCreateWithFlags(&s_evJoin, cudaEventDisableTiming);
        cudaEventCreateWithFlags(&s_evPrep1, cudaEventDisableTiming);
        cudaEventCreateWithFlags(&s_evLo1, cudaEventDisableTiming);
        cudaEventCreateWithFlags(&s_evPrep2, cudaEventDisableTiming);
        cudaEventCreateWithFlags(&s_evLo2, cudaEventDisableTiming);
        init_done = 1;
    }

    int gE = (E + 255) / 256;
    int gN = (N + 255) / 256;
    int gSp = (N * 32 + 255) / 256;
    int gM = (N + 127) / 128;

    const int LD1 = KCH * FH;    // 2048
    const int LD2 = KCH * FOUT;  // 512

    // ---- fork: graph build + W2 concat on side stream ----
    cudaEventRecord(s_evFork, 0);
    cudaStreamWaitEvent(s_side, s_evFork, 0);

    init_zero<<<gN, 256, 0, s_side>>>(N);
    detect_dtype<<<gE, 256, 0, s_side>>>((const int*)ei, E);
    degree_kernel<<<gE, 256, 0, s_side>>>(ei, E);
    dinv_kernel<<<gN, 256, 0, s_side>>>(N);
    scan_kernel<<<1, 1024, 0, s_side>>>(N);
    scatter_kernel<<<gE, 256, 0, s_side>>>(ei, E);
    concat_w2_t<<<((KCH * FOUT) * FH + 255) / 256, 256, 0, s_side>>>(W2, W2t);
    cudaEventRecord(s_evJoin, s_side);

    cvt_xh<<<(N * FIN / 2 + 255) / 256, 256>>>((const float2*)x, (__half2*)Xh, N * FIN / 2);
    concat_w1_t<<<((KCH * FH) * FIN + 255) / 256, 256>>>(W1, W1t);
    // GEMM1 hi half: slices 8..15 (n in [1024,2048))
    gemm_f16<<<dim3(gM, 8), 256, GEMM_SMEM>>>(Xh, W1t + (size_t)1024 * 128, S1 + 1024, N, LD1);
    cudaEventRecord(s_evPrep1, 0);

    // GEMM1 lo half on side stream, concurrent with chain steps 0..6
    cudaStreamWaitEvent(s_side, s_evPrep1, 0);
    gemm_f16<<<dim3(gM, 8), 256, GEMM_SMEM, s_side>>>(Xh, W1t, S1, N, LD1);
    cudaEventRecord(s_evLo1, s_side);

    cudaStreamWaitEvent(0, s_evJoin, 0);   // graph build done before Clenshaw

    __half* hb[3] = {H0, H1, H2};

    // ======== Layer 1 Clenshaw: fp16-only b-chain ========
    {
        // steps 0..6 use slices 15..8 only (hi half)
        cheb_spmm128<0><<<gSp, 256>>>(nullptr, (const float4*)(S1 + 15 * FH), LD1 / 4,
                                      nullptr, nullptr, 0,
                                      (const float4*)(S1 + 14 * FH), LD1 / 4,
                                      (uint2*)hb[0], nullptr, nullptr, 2.f, N, 0);
        cheb_spmm128<1><<<gSp, 256>>>((const uint2*)hb[0], nullptr, 0,
                                      nullptr, (const float4*)(S1 + 15 * FH), LD1 / 4,
                                      (const float4*)(S1 + 13 * FH), LD1 / 4,
                                      (uint2*)hb[1], nullptr, nullptr, 2.f, N, 0);
        int cur = 1;
        for (int k = 12; k >= 8; k--) {
            int prv = (cur + 2) % 3;
            int nxt = (cur + 1) % 3;
            cheb_spmm128<1><<<gSp, 256>>>((const uint2*)hb[cur], nullptr, 0,
                                          (const uint2*)hb[prv], nullptr, 0,
                                          (const float4*)(S1 + k * FH), LD1 / 4,
                                          (uint2*)hb[nxt], nullptr, nullptr, 2.f, N, 0);
            cur = nxt;
        }
        // join: lo-half GEMM must be done before slice 7 is read
        cudaStreamWaitEvent(0, s_evLo1, 0);
        for (int k = 7; k >= 1; k--) {
            int prv = (cur + 2) % 3;
            int nxt = (cur + 1) % 3;
            cheb_spmm128<1><<<gSp, 256>>>((const uint2*)hb[cur], nullptr, 0,
                                          (const uint2*)hb[prv], nullptr, 0,
                                          (const float4*)(S1 + k * FH), LD1 / 4,
                                          (uint2*)hb[nxt], nullptr, nullptr, 2.f, N, 0);
            cur = nxt;
        }
        int prv = (cur + 2) % 3;
        cheb_spmm128<1><<<gSp, 256>>>((const uint2*)hb[cur], nullptr, 0,
                                      (const uint2*)hb[prv], nullptr, 0,
                                      (const float4*)S1, LD1 / 4,
                                      nullptr, (float4*)H, (const float4*)b1v, 1.f, N, 1);
    }
    // BN+ReLU -> fp16 H into H0 (H0 stays READ-ONLY through all of layer 2)
    bn_apply_relu<<<(N * FH + 255) / 256, 256>>>(H, nullptr, H0, g1, be1, bns1, bnq1, N, FH, 1);

    // ======== Layer 2 ========
    // GEMM2 hi half: slices 8..15 (n in [256,512))
    gemm_f16<<<dim3(gM, 2), 256, GEMM_SMEM>>>(H0, W2t + (size_t)256 * 128, S2 + 256, N, LD2);
    cudaEventRecord(s_evPrep2, 0);
    cudaStreamWaitEvent(s_side, s_evPrep2, 0);
    gemm_f16<<<dim3(gM, 2), 256, GEMM_SMEM, s_side>>>(H0, W2t, S2, N, LD2);
    cudaEventRecord(s_evLo2, s_side);
    {
        // ring excludes H0 (still being read by side-stream GEMM2-lo)
        __half* hb2[3] = {H1, H2, H3};
        cheb_spmm32<0><<<gSp, 256>>>(nullptr, S2 + 15 * FOUT, LD2,
                                     nullptr, nullptr, 0,
                                     S2 + 14 * FOUT, LD2,
                                     hb2[0], nullptr, nullptr, 2.f, N, 0);
        cheb_spmm32<1><<<gSp, 256>>>(hb2[0], nullptr, 0,
                                     nullptr, S2 + 15 * FOUT, LD2,
                                     S2 + 13 * FOUT, LD2,
                                     hb2[1], nullptr, nullptr, 2.f, N, 0);
        int cur = 1;
        for (int k = 12; k >= 8; k--) {
            int prv = (cur + 2) % 3;
            int nxt = (cur + 1) % 3;
            cheb_spmm32<1><<<gSp, 256>>>(hb2[cur], nullptr, 0,
                                         hb2[prv], nullptr, 0,
                                         S2 + k * FOUT, LD2,
                                         hb2[nxt], nullptr, nullptr, 2.f, N, 0);
            cur = nxt;
        }
        cudaStreamWaitEvent(0, s_evLo2, 0);
        for (int k = 7; k >= 1; k--) {
            int prv = (cur + 2) % 3;
            int nxt = (cur + 1) % 3;
            cheb_spmm32<1><<<gSp, 256>>>(hb2[cur], nullptr, 0,
                                         hb2[prv], nullptr, 0,
                                         S2 + k * FOUT, LD2,
                                         hb2[nxt], nullptr, nullptr, 2.f, N, 0);
            cur = nxt;
        }
        int prv = (cur + 2) % 3;
        cheb_spmm32<1><<<gSp, 256>>>(hb2[cur], nullptr, 0,
                                     hb2[prv], nullptr, 0,
                                     S2, LD2,
                                     nullptr, out, b2v, 1.f, N, 1);
    }
    bn_apply_relu<<<(N * FOUT + 255) / 256, 256>>>(out, out, nullptr, g2, be2, bns2, bnq2, N, FOUT, 0);
}

// round 15
// speedup vs baseline: 1.0128x; 1.0128x over previous
#include <cuda_runtime.h>
#include <cuda_fp16.h>
#include <cstdint>

#define NN   50000
#define EE   800000
#define FIN  128
#define FH   128
#define FOUT 32
#define KCH  16

// ---------------- device scratch ----------------
__device__ float  g_S1[NN * (KCH * FH)];    // 50000 x 2048
__device__ float  g_S2[NN * (KCH * FOUT)];  // 50000 x 512
__device__ __half g_Xh[NN * FIN];           // fp16 x
__device__ __half g_W1t[(KCH * FH) * FIN];  // W1 transposed: [n][k]
__device__ __half g_W2t[(KCH * FOUT) * FH]; // W2 transposed
__device__ __half g_h0[NN * FH];
__device__ __half g_h1[NN * FH];
__device__ __half g_h2[NN * FH];
__device__ __half g_h3[NN * FH];            // fp16 twin of S1 slice 15 (b15)
__device__ float  g_H [NN * FH];
__device__ int    g_degi[NN];
__device__ int    g_cnt [NN];
__device__ int    g_rowptr[NN + 1];
__device__ int    g_cursor[NN];
__device__ float  g_dinv[NN];
__device__ int2   g_colval[EE];
__device__ float  g_bnsum1[FH];
__device__ float  g_bnsq1 [FH];
__device__ float  g_bnsum2[FOUT];
__device__ float  g_bnsq2 [FOUT];
__device__ int    g_is32;

// ---------------- helpers ----------------
__device__ __forceinline__ void mma_f16(float* c, const unsigned* a, const unsigned* b) {
    asm volatile("mma.sync.aligned.m16n8k16.row.col.f32.f16.f16.f32 "
        "{%0,%1,%2,%3}, {%4,%5,%6,%7}, {%8,%9}, {%0,%1,%2,%3};"
        : "+f"(c[0]), "+f"(c[1]), "+f"(c[2]), "+f"(c[3])
        : "r"(a[0]), "r"(a[1]), "r"(a[2]), "r"(a[3]), "r"(b[0]), "r"(b[1]));
}

__device__ __forceinline__ void cp_async16(uint32_t dst, const void* src, int szbytes) {
    asm volatile("cp.async.cg.shared.global [%0], [%1], 16, %2;"
                 :: "r"(dst), "l"(src), "r"(szbytes));
}
__device__ __forceinline__ void cp_commit() {
    asm volatile("cp.async.commit_group;");
}
template <int NW>
__device__ __forceinline__ void cp_wait() {
    asm volatile("cp.async.wait_group %0;" :: "n"(NW));
}

// ---------------- build kernels ----------------
__global__ void init_zero(int N) {
    int i = blockIdx.x * blockDim.x + threadIdx.x;
    if (i < N) { g_degi[i] = 0; g_cnt[i] = 0; }
    if (i < FH)   { g_bnsum1[i] = 0.f; g_bnsq1[i] = 0.f; }
    if (i < FOUT) { g_bnsum2[i] = 0.f; g_bnsq2[i] = 0.f; }
    if (i == 0) g_is32 = 0;
}

__global__ void detect_dtype(const int* __restrict__ p, int E) {
    int i = blockIdx.x * blockDim.x + threadIdx.x;
    if (i < E) {
        if (p[2 * i + 1] != 0) g_is32 = 1;
    }
}

__global__ void cvt_xh(const float2* __restrict__ x, __half2* __restrict__ xh, int n2) {
    int i = blockIdx.x * blockDim.x + threadIdx.x;
    if (i >= n2) return;
    float2 v = x[i];
    xh[i] = __floats2half2_rn(v.x, v.y);
}

__device__ __forceinline__ void load_edge(const void* ei, int E, int e, int& s, int& d) {
    if (g_is32) {
        const int* p = (const int*)ei;
        s = p[e]; d = p[E + e];
    } else {
        const long long* p = (const long long*)ei;
        s = (int)p[e]; d = (int)p[E + e];
    }
}

__global__ void degree_kernel(const void* __restrict__ ei, int E) {
    int e = blockIdx.x * blockDim.x + threadIdx.x;
    if (e >= E) return;
    int s, d; load_edge(ei, E, e, s, d);
    if (s != d) { atomicAdd(&g_degi[s], 1); atomicAdd(&g_cnt[d], 1); }
}

__global__ void dinv_kernel(int N) {
    int i = blockIdx.x * blockDim.x + threadIdx.x;
    if (i >= N) return;
    int dg = g_degi[i];
    g_dinv[i] = (dg > 0) ? rsqrtf((float)dg) : 0.f;
}

__global__ void scan_kernel(int N) {
    __shared__ int warpsum[32];
    __shared__ int s_carry;
    __shared__ int s_chunk;
    int t = threadIdx.x, lane = t & 31, wid = t >> 5;
    if (t == 0) s_carry = 0;
    __syncthreads();
    for (int base = 0; base < N; base += 1024) {
        int idx = base + t;
        int v = (idx < N) ? g_cnt[idx] : 0;
        int x = v;
        #pragma unroll
        for (int off = 1; off < 32; off <<= 1) {
            int y = __shfl_up_sync(0xffffffffu, x, off);
            if (lane >= off) x += y;
        }
        if (lane == 31) warpsum[wid] = x;
        __syncthreads();
        if (wid == 0) {
            int w = warpsum[lane];
            int xw = w;
            #pragma unroll
            for (int off = 1; off < 32; off <<= 1) {
                int y = __shfl_up_sync(0xffffffffu, xw, off);
                if (lane >= off) xw += y;
            }
            warpsum[lane] = xw - w;
            if (lane == 31) s_chunk = xw;
        }
        __syncthreads();
        int excl = s_carry + warpsum[wid] + x - v;
        if (idx < N) { g_rowptr[idx] = excl; g_cursor[idx] = excl; }
        __syncthreads();
        if (t == 0) s_carry += s_chunk;
        __syncthreads();
    }
    if (threadIdx.x == 0) g_rowptr[N] = s_carry;
}

__global__ void scatter_kernel(const void* __restrict__ ei, int E) {
    int e = blockIdx.x * blockDim.x + threadIdx.x;
    if (e >= E) return;
    int s, d; load_edge(ei, E, e, s, d);
    if (s != d) {
        int pos = atomicAdd(&g_cursor[d], 1);
        float v = -g_dinv[s] * g_dinv[d];
        g_colval[pos] = make_int2(s, __float_as_int(v));
    }
}

// ---------------- weight concat: transpose to [n][k] fp16 ----------------
__global__ void concat_w1_t(const float* __restrict__ W, __half* __restrict__ Wt) {
    int j = blockIdx.x * blockDim.x + threadIdx.x;
    if (j >= (KCH * FH) * FIN) return;
    int n = j >> 7;
    int f = j & 127;
    int k = n >> 7;
    int o = n & 127;
    Wt[j] = __float2half_rn(W[k * (FIN * FH) + f * FH + o]);
}

__global__ void concat_w2_t(const float* __restrict__ W, __half* __restrict__ Wt) {
    int j = blockIdx.x * blockDim.x + threadIdx.x;
    if (j >= (KCH * FOUT) * FH) return;
    int n = j >> 7;
    int f = j & 127;
    int k = n >> 5;
    int o = n & 31;
    Wt[j] = __float2half_rn(W[k * (FH * FOUT) + f * FOUT + o]);
}

// ---------------- FP16 GEMM: C[N,NC] = A[N,128] @ Bt[NC,128]^T ----------------
// Optional fp16 dual-write: global columns >= chColLo also stored (compact,
// row width NC-chColLo) into Ch. chColLo < 0 disables.
#define SH_STRIDE 40
#define SA_STAGE_B (128 * SH_STRIDE * 2)
#define SB_STAGE_B (128 * SH_STRIDE * 2)
#define GEMM_SMEM (2 * (SA_STAGE_B + SB_STAGE_B))

__global__ __launch_bounds__(256, 2) void gemm_f16(const __half* __restrict__ A,
                                                   const __half* __restrict__ Bt,
                                                   float* __restrict__ C,
                                                   __half2* __restrict__ Ch,
                                                   int chColLo,
                                                   int N, int NC) {
    extern __shared__ char smem[];
    char* sA = smem;
    char* sB = smem + 2 * SA_STAGE_B;
    uint32_t sA_u = (uint32_t)__cvta_generic_to_shared(sA);
    uint32_t sB_u = (uint32_t)__cvta_generic_to_shared(sB);

    int t = threadIdx.x;
    int lane = t & 31;
    int warp = t >> 5;
    int tig = lane & 3;
    int grp = lane >> 2;
    int wm0 = (warp & 1) * 64;
    int wn0 = (warp >> 1) * 32;
    int bm0 = blockIdx.x * 128;
    int bn0 = blockIdx.y * 128;

    float c[4][4][4];
    #pragma unroll
    for (int mi = 0; mi < 4; mi++)
        #pragma unroll
        for (int ni = 0; ni < 4; ni++)
            #pragma unroll
            for (int r = 0; r < 4; r++) c[mi][ni][r] = 0.f;

    auto prefetch = [&](int stage, int kt) {
        #pragma unroll
        for (int i = 0; i < 2; i++) {
            int id = t + i * 256;
            int row = id >> 2, c4 = id & 3;
            int gr = bm0 + row;
            int ok = (gr < N);
            int grs = ok ? gr : 0;
            uint32_t dst = sA_u + stage * SA_STAGE_B + row * 80 + c4 * 16;
            cp_async16(dst, &A[(size_t)grs * 128 + kt + c4 * 8], ok ? 16 : 0);
        }
        #pragma unroll
        for (int i = 0; i < 2; i++) {
            int id = t + i * 256;
            int row = id >> 2, c4 = id & 3;
            uint32_t dst = sB_u + stage * SB_STAGE_B + row * 80 + c4 * 16;
            cp_async16(dst, &Bt[(size_t)(bn0 + row) * 128 + kt + c4 * 8], 16);
        }
        cp_commit();
    };

    prefetch(0, 0);

    #pragma unroll
    for (int it = 0; it < 4; it++) {
        if (it < 3) prefetch((it + 1) & 1, (it + 1) * 32);
        if (it < 3) cp_wait<1>(); else cp_wait<0>();
        __syncthreads();

        const unsigned* cA = (const unsigned*)(sA + (it & 1) * SA_STAGE_B);
        const unsigned* cB = (const unsigned*)(sB + (it & 1) * SB_STAGE_B);
        #pragma unroll
        for (int kh = 0; kh < 2; kh++) {
            int ko = kh * 8;
            unsigned a[4][4], b[4][2];
            #pragma unroll
            for (int mi = 0; mi < 4; mi++) {
                int row = wm0 + mi * 16 + grp;
                int base = row * 20 + ko + tig;
                a[mi][0] = cA[base];
                a[mi][1] = cA[base + 8 * 20];
                a[mi][2] = cA[base + 4];
                a[mi][3] = cA[base + 8 * 20 + 4];
            }
            #pragma unroll
            for (int ni = 0; ni < 4; ni++) {
                int nn = wn0 + ni * 8 + grp;
                int nb = nn * 20 + ko + tig;
                b[ni][0] = cB[nb];
                b[ni][1] = cB[nb + 4];
            }
            #pragma unroll
            for (int mi = 0; mi < 4; mi++)
                #pragma unroll
                for (int ni = 0; ni < 4; ni++)
                    mma_f16(c[mi][ni], a[mi], b[ni]);
        }
        __syncthreads();
    }

    int chW = NC - chColLo;
    #pragma unroll
    for (int mi = 0; mi < 4; mi++) {
        #pragma unroll
        for (int ni = 0; ni < 4; ni++) {
            int gr = bm0 + wm0 + mi * 16 + grp;
            int gc = bn0 + wn0 + ni * 8 + 2 * tig;
            if (gr < N) {
                *(float2*)&C[(size_t)gr * NC + gc] = make_float2(c[mi][ni][0], c[mi][ni][1]);
                if (Ch && gc >= chColLo)
                    Ch[((size_t)gr * chW + (gc - chColLo)) >> 1] =
                        __floats2half2_rn(c[mi][ni][0], c[mi][ni][1]);
            }
            if (gr + 8 < N) {
                *(float2*)&C[(size_t)(gr + 8) * NC + gc] = make_float2(c[mi][ni][2], c[mi][ni][3]);
                if (Ch && gc >= chColLo)
                    Ch[((size_t)(gr + 8) * chW + (gc - chColLo)) >> 1] =
                        __floats2half2_rn(c[mi][ni][2], c[mi][ni][3]);
            }
        }
    }
}

// ---------------- Clenshaw SpMM, 128 features, fp16 chain ----------------
template <int USEH>
__global__ void cheb_spmm128(const uint2* __restrict__ b1h,
                             const float4* __restrict__ b1f, int ldb1f,
                             const uint2* __restrict__ b2h,
                             const float4* __restrict__ b2f, int ldb2f,
                             const float4* __restrict__ S, int ldS,
                             uint2* __restrict__ dsth,
                             float4* __restrict__ dstf,
                             const float4* __restrict__ bias,
                             float two, int N, int stats) {
    __shared__ float ssum[128], ssq[128];
    int row = (blockIdx.x * blockDim.x + threadIdx.x) >> 5;
    int lane = threadIdx.x & 31;
    if (stats) {
        if (threadIdx.x < 128) { ssum[threadIdx.x] = 0.f; ssq[threadIdx.x] = 0.f; }
        __syncthreads();
    }
    if (row < N) {
        int start = g_rowptr[row], end = g_rowptr[row + 1];
        float4 acc = make_float4(0.f, 0.f, 0.f, 0.f);
        for (int i = start; i < end; i += 32) {
            int nb = min(32, end - i);
            int c = 0; float v = 0.f;
            if (lane < nb) {
                int2 cv = g_colval[i + lane];
                c = cv.x; v = __int_as_float(cv.y);
            }
            #pragma unroll 4
            for (int j = 0; j < nb; j++) {
                int   cc = __shfl_sync(0xffffffffu, c, j);
                float vv = __shfl_sync(0xffffffffu, v, j);
                if (USEH) {
                    uint2 u = b1h[(size_t)cc * 32 + lane];
                    float2 f01 = __half22float2(*(const __half2*)&u.x);
                    float2 f23 = __half22float2(*(const __half2*)&u.y);
                    acc.x = fmaf(vv, f01.x, acc.x);
                    acc.y = fmaf(vv, f01.y, acc.y);
                    acc.z = fmaf(vv, f23.x, acc.z);
                    acc.w = fmaf(vv, f23.y, acc.w);
                } else {
                    float4 xr = b1f[(size_t)cc * ldb1f + lane];
                    acc.x = fmaf(vv, xr.x, acc.x);
                    acc.y = fmaf(vv, xr.y, acc.y);
                    acc.z = fmaf(vv, xr.z, acc.z);
                    acc.w = fmaf(vv, xr.w, acc.w);
                }
            }
        }
        float4 s = S[(size_t)row * ldS + lane];
        float4 r;
        r.x = fmaf(two, acc.x, s.x);
        r.y = fmaf(two, acc.y, s.y);
        r.z = fmaf(two, acc.z, s.z);
        r.w = fmaf(two, acc.w, s.w);
        if (b2h) {
            uint2 u = b2h[(size_t)row * 32 + lane];
            float2 f01 = __half22float2(*(const __half2*)&u.x);
            float2 f23 = __half22float2(*(const __half2*)&u.y);
            r.x -= f01.x; r.y -= f01.y; r.z -= f23.x; r.w -= f23.y;
        } else if (b2f) {
            float4 tt = b2f[(size_t)row * ldb2f + lane];
            r.x -= tt.x; r.y -= tt.y; r.z -= tt.z; r.w -= tt.w;
        }
        if (bias) {
            float4 bb = bias[lane];
            r.x += bb.x; r.y += bb.y; r.z += bb.z; r.w += bb.w;
        }
        if (dsth) {
            __half2 h01 = __floats2half2_rn(r.x, r.y);
            __half2 h23 = __floats2half2_rn(r.z, r.w);
            uint2 u;
            u.x = *(unsigned*)&h01;
            u.y = *(unsigned*)&h23;
            dsth[(size_t)row * 32 + lane] = u;
        }
        if (dstf) dstf[(size_t)row * 32 + lane] = r;
        if (stats) {
            int f = lane * 4;
            atomicAdd(&ssum[f],     r.x); atomicAdd(&ssq[f],     r.x * r.x);
            atomicAdd(&ssum[f + 1], r.y); atomicAdd(&ssq[f + 1], r.y * r.y);
            atomicAdd(&ssum[f + 2], r.z); atomicAdd(&ssq[f + 2], r.z * r.z);
            atomicAdd(&ssum[f + 3], r.w); atomicAdd(&ssq[f + 3], r.w * r.w);
        }
    }
    if (stats) {
        __syncthreads();
        if (threadIdx.x < 128) {
            atomicAdd(&g_bnsum1[threadIdx.x], ssum[threadIdx.x]);
            atomicAdd(&g_bnsq1 [threadIdx.x], ssq [threadIdx.x]);
        }
    }
}

// ---------------- Clenshaw SpMM, 32 features, fp16 chain ----------------
template <int USEH>
__global__ void cheb_spmm32(const __half* __restrict__ b1h,
                            const float* __restrict__ b1f, int ldb1f,
                            const __half* __restrict__ b2h,
                            const float* __restrict__ b2f, int ldb2f,
                            const float* __restrict__ S, int ldS,
                            __half* __restrict__ dsth,
                            float* __restrict__ dstf,
                            const float* __restrict__ bias,
                            float two, int N, int stats) {
    __shared__ float ssum[32], ssq[32];
    int row = (blockIdx.x * blockDim.x + threadIdx.x) >> 5;
    int lane = threadIdx.x & 31;
    if (stats) {
        if (threadIdx.x < 32) { ssum[threadIdx.x] = 0.f; ssq[threadIdx.x] = 0.f; }
        __syncthreads();
    }
    if (row < N) {
        int start = g_rowptr[row], end = g_rowptr[row + 1];
        float acc = 0.f;
        for (int i = start; i < end; i += 32) {
            int nb = min(32, end - i);
            int c = 0; float v = 0.f;
            if (lane < nb) {
                int2 cv = g_colval[i + lane];
                c = cv.x; v = __int_as_float(cv.y);
            }
            #pragma unroll 4
            for (int j = 0; j < nb; j++) {
                int   cc = __shfl_sync(0xffffffffu, c, j);
                float vv = __shfl_sync(0xffffffffu, v, j);
                float xv;
                if (USEH) xv = __half2float(b1h[(size_t)cc * 32 + lane]);
                else      xv = b1f[(size_t)cc * ldb1f + lane];
                acc = fmaf(vv, xv, acc);
            }
        }
        float r = fmaf(two, acc, S[(size_t)row * ldS + lane]);
        if (b2h)      r -= __half2float(b2h[(size_t)row * 32 + lane]);
        else if (b2f) r -= b2f[(size_t)row * ldb2f + lane];
        if (bias) r += bias[lane];
        if (dsth) dsth[(size_t)row * 32 + lane] = __float2half_rn(r);
        if (dstf) dstf[(size_t)row * 32 + lane] = r;
        if (stats) {
            atomicAdd(&ssum[lane], r);
            atomicAdd(&ssq [lane], r * r);
        }
    }
    if (stats) {
        __syncthreads();
        if (threadIdx.x < 32) {
            atomicAdd(&g_bnsum2[threadIdx.x], ssum[threadIdx.x]);
            atomicAdd(&g_bnsq2 [threadIdx.x], ssq [threadIdx.x]);
        }
    }
}

// ---------------- BatchNorm apply ----------------
__global__ void bn_apply_relu(const float* __restrict__ X,
                              float* __restrict__ Yf, __half* __restrict__ Yh,
                              const float* __restrict__ gamma, const float* __restrict__ beta,
                              const float* __restrict__ bnsum, const float* __restrict__ bnsq,
                              int N, int C, int mode) {
    int i = blockIdx.x * blockDim.x + threadIdx.x;
    if (i >= N * C) return;
    int c = i % C;
    float invN = 1.f / (float)N;
    float mu  = bnsum[c] * invN;
    float var = bnsq[c] * invN - mu * mu;
    float y = fmaf(gamma[c] * rsqrtf(var + 1e-5f), X[i] - mu, beta[c]);
    y = fmaxf(y, 0.f);
    if (mode) Yh[i] = __float2half_rn(y);
    else      Yf[i] = y;
}

// ---------------- host ----------------
extern "C" void kernel_launch(void* const* d_in, const int* in_sizes, int n_in,
                              void* d_out, int out_size) {
    const float* x    = (const float*)d_in[0];
    const void*  ei   = d_in[1];
    const float* W1   = (const float*)d_in[2];
    const float* b1v  = (const float*)d_in[3];
    const float* W2   = (const float*)d_in[4];
    const float* b2v  = (const float*)d_in[5];
    const float* g1   = (const float*)d_in[6];
    const float* be1  = (const float*)d_in[7];
    const float* g2   = (const float*)d_in[8];
    const float* be2  = (const float*)d_in[9];
    float* out = (float*)d_out;

    int N = in_sizes[0] / FIN;
    int E = in_sizes[1] / 2;

    void* pv;
    cudaGetSymbolAddress(&pv, g_S1);  float*  S1  = (float*)pv;
    cudaGetSymbolAddress(&pv, g_S2);  float*  S2  = (float*)pv;
    cudaGetSymbolAddress(&pv, g_Xh);  __half* Xh  = (__half*)pv;
    cudaGetSymbolAddress(&pv, g_W1t); __half* W1t = (__half*)pv;
    cudaGetSymbolAddress(&pv, g_W2t); __half* W2t = (__half*)pv;
    cudaGetSymbolAddress(&pv, g_h0);  __half* H0  = (__half*)pv;
    cudaGetSymbolAddress(&pv, g_h1);  __half* H1  = (__half*)pv;
    cudaGetSymbolAddress(&pv, g_h2);  __half* H2  = (__half*)pv;
    cudaGetSymbolAddress(&pv, g_h3);  __half* H3  = (__half*)pv;
    cudaGetSymbolAddress(&pv, g_H);   float*  H   = (float*)pv;
    cudaGetSymbolAddress(&pv, g_bnsum1); float* bns1 = (float*)pv;
    cudaGetSymbolAddress(&pv, g_bnsq1);  float* bnq1 = (float*)pv;
    cudaGetSymbolAddress(&pv, g_bnsum2); float* bns2 = (float*)pv;
    cudaGetSymbolAddress(&pv, g_bnsq2);  float* bnq2 = (float*)pv;

    static int init_done = 0;
    static cudaStream_t s_side = nullptr;
    static cudaEvent_t s_evFork = nullptr, s_evJoin = nullptr;
    if (!init_done) {
        cudaFuncSetAttribute(gemm_f16, cudaFuncAttributeMaxDynamicSharedMemorySize, GEMM_SMEM);
        cudaStreamCreateWithFlags(&s_side, cudaStreamNonBlocking);
        cudaEventCreateWithFlags(&s_evFork, cudaEventDisableTiming);
        cudaEventCreateWithFlags(&s_evJoin, cudaEventDisableTiming);
        init_done = 1;
    }

    int gE = (E + 255) / 256;
    int gN = (N + 255) / 256;
    int gSp = (N * 32 + 255) / 256;
    int gM = (N + 127) / 128;

    const int LD1 = KCH * FH;    // 2048
    const int LD2 = KCH * FOUT;  // 512

    // ---- fork: graph build + W2 concat on side stream ----
    cudaEventRecord(s_evFork, 0);
    cudaStreamWaitEvent(s_side, s_evFork, 0);

    init_zero<<<gN, 256, 0, s_side>>>(N);
    detect_dtype<<<gE, 256, 0, s_side>>>((const int*)ei, E);
    degree_kernel<<<gE, 256, 0, s_side>>>(ei, E);
    dinv_kernel<<<gN, 256, 0, s_side>>>(N);
    scan_kernel<<<1, 1024, 0, s_side>>>(N);
    scatter_kernel<<<gE, 256, 0, s_side>>>(ei, E);
    concat_w2_t<<<((KCH * FOUT) * FH + 255) / 256, 256, 0, s_side>>>(W2, W2t);
    cudaEventRecord(s_evJoin, s_side);

    cvt_xh<<<(N * FIN / 2 + 255) / 256, 256>>>((const float2*)x, (__half2*)Xh, N * FIN / 2);
    concat_w1_t<<<((KCH * FH) * FIN + 255) / 256, 256>>>(W1, W1t);
    // GEMM1: full, with fp16 dual-write of slice 15 (cols >= 1920) into H3
    gemm_f16<<<dim3(gM, LD1 / 128), 256, GEMM_SMEM>>>(Xh, W1t, S1, (__half2*)H3, 15 * FH, N, LD1);

    cudaStreamWaitEvent(0, s_evJoin, 0);   // graph build done before Clenshaw

    __half* hb[3] = {H0, H1, H2};

    // ======== Layer 1 Clenshaw: fp16-only b-chain (b15 = H3 fp16 twin) ========
    {
        // step 0: b1 = b15 fp16 (H3), no b2
        cheb_spmm128<1><<<gSp, 256>>>((const uint2*)H3, nullptr, 0,
                                      nullptr, nullptr, 0,
                                      (const float4*)(S1 + 14 * FH), LD1 / 4,
                                      (uint2*)hb[0], nullptr, nullptr, 2.f, N, 0);
        // step 1: b2 = b15 fp16 (H3)
        cheb_spmm128<1><<<gSp, 256>>>((const uint2*)hb[0], nullptr, 0,
                                      (const uint2*)H3, nullptr, 0,
                                      (const float4*)(S1 + 13 * FH), LD1 / 4,
                                      (uint2*)hb[1], nullptr, nullptr, 2.f, N, 0);
        int cur = 1;
        for (int k = 12; k >= 1; k--) {
            int prv = (cur + 2) % 3;
            int nxt = (cur + 1) % 3;
            cheb_spmm128<1><<<gSp, 256>>>((const uint2*)hb[cur], nullptr, 0,
                                          (const uint2*)hb[prv], nullptr, 0,
                                          (const float4*)(S1 + k * FH), LD1 / 4,
                                          (uint2*)hb[nxt], nullptr, nullptr, 2.f, N, 0);
            cur = nxt;
        }
        int prv = (cur + 2) % 3;
        cheb_spmm128<1><<<gSp, 256>>>((const uint2*)hb[cur], nullptr, 0,
                                      (const uint2*)hb[prv], nullptr, 0,
                                      (const float4*)S1, LD1 / 4,
                                      nullptr, (float4*)H, (const float4*)b1v, 1.f, N, 1);
    }
    // BN+ReLU -> fp16 H into H0 (GEMM2 reads it serially before chain reuses rings)
    bn_apply_relu<<<(N * FH + 255) / 256, 256>>>(H, nullptr, H0, g1, be1, bns1, bnq1, N, FH, 1);

    // ======== Layer 2 (serial, as R11) ========
    gemm_f16<<<dim3(gM, LD2 / 128), 256, GEMM_SMEM>>>(H0, W2t, S2, nullptr, 0, N, LD2);
    {
        __half* hb2[3] = {H0, H1, H2};
        cheb_spmm32<0><<<gSp, 256>>>(nullptr, S2 + 15 * FOUT, LD2,
                                     nullptr, nullptr, 0,
                                     S2 + 14 * FOUT, LD2,
                                     hb2[0], nullptr, nullptr, 2.f, N, 0);
        cheb_spmm32<1><<<gSp, 256>>>(hb2[0], nullptr, 0,
                                     nullptr, S2 + 15 * FOUT, LD2,
                                     S2 + 13 * FOUT, LD2,
                                     hb2[1], nullptr, nullptr, 2.f, N, 0);
        int cur = 1;
        for (int k = 12; k >= 1; k--) {
            int prv = (cur + 2) % 3;
            int nxt = (cur + 1) % 3;
            cheb_spmm32<1><<<gSp, 256>>>(hb2[cur], nullptr, 0,
                                         hb2[prv], nullptr, 0,
                                         S2 + k * FOUT, LD2,
                                         hb2[nxt], nullptr, nullptr, 2.f, N, 0);
            cur = nxt;
        }
        int prv = (cur + 2) % 3;
        cheb_spmm32<1><<<gSp, 256>>>(hb2[cur], nullptr, 0,
                                     hb2[prv], nullptr, 0,
                                     S2, LD2,
                                     nullptr, out, b2v, 1.f, N, 1);
    }
    bn_apply_relu<<<(N * FOUT + 255) / 256, 256>>>(out, out, nullptr, g2, be2, bns2, bnq2, N, FOUT, 0);
}